// round 15
// baseline (speedup 1.0000x reference)
#include <cuda_runtime.h>
#include <cuda_bf16.h>
#include <cuda_fp16.h>
#include <cstdint>

// ---------------------------------------------------------------------------
// MHSA: B=8, N=1024, D=768, H=12, HD=64.
// R15 = R13 (best, 477.7us; R14 term-major reverted as neutral) + attention
// converted to 3-STAGE K/V cp.async with ONE __syncthreads per tile and
// prefetch issued right after the barrier (R7 GEMM discipline).  smem/CTA =
// 114688 B; 2 CTAs/SM = 229376 (+2KB reserve) <= 228KB -- fits by ~2KB.
// Math unchanged: rel_err must be exactly 3.413968e-4.
// ---------------------------------------------------------------------------

constexpr int CB  = 8;
constexpr int CN  = 1024;
constexpr int CD  = 768;
constexpr int CH  = 12;
constexpr int CHD = 64;
constexpr int CM  = CB * CN;   // 8192
constexpr int BH  = CB * CH;   // 96
constexpr int CD2 = CD * 2;

__device__ __nv_bfloat16 g_qh[BH * CN * CHD], g_ql[BH * CN * CHD];
__device__ __nv_bfloat16 g_kh[BH * CN * CHD], g_kl[BH * CN * CHD];
__device__ __half        g_vt[BH * CHD * CN];
__device__ __nv_bfloat16 g_xs[CM * CD2];
__device__ __half        g_xh[CM * CD];
__device__ __half        g_ash[CM * CD];
__device__ __nv_bfloat16 g_wt[2 * CD * CD2];
__device__ __half        g_wtv[CD * CD2];
__device__ __half        g_wto[CD * CD2];

// ======================= PTX helpers =======================================
__device__ __forceinline__ uint32_t smem_u32(const void* p) {
    uint32_t a;
    asm("{ .reg .u64 t; cvta.to.shared.u64 t, %1; cvt.u32.u64 %0, t; }"
        : "=r"(a) : "l"(p));
    return a;
}
__device__ __forceinline__ void ldsm_x4(uint32_t& r0, uint32_t& r1,
                                        uint32_t& r2, uint32_t& r3,
                                        uint32_t addr) {
    asm volatile("ldmatrix.sync.aligned.m8n8.x4.shared.b16 {%0,%1,%2,%3}, [%4];"
                 : "=r"(r0), "=r"(r1), "=r"(r2), "=r"(r3) : "r"(addr));
}
__device__ __forceinline__ void mma16816(float* c, const uint32_t* a,
                                         uint32_t b0, uint32_t b1) {
    asm volatile(
        "mma.sync.aligned.m16n8k16.row.col.f32.bf16.bf16.f32 "
        "{%0,%1,%2,%3}, {%4,%5,%6,%7}, {%8,%9}, {%0,%1,%2,%3};"
        : "+f"(c[0]), "+f"(c[1]), "+f"(c[2]), "+f"(c[3])
        : "r"(a[0]), "r"(a[1]), "r"(a[2]), "r"(a[3]), "r"(b0), "r"(b1));
}
__device__ __forceinline__ void mma16816h(float* c, const uint32_t* a,
                                          uint32_t b0, uint32_t b1) {
    asm volatile(
        "mma.sync.aligned.m16n8k16.row.col.f32.f16.f16.f32 "
        "{%0,%1,%2,%3}, {%4,%5,%6,%7}, {%8,%9}, {%0,%1,%2,%3};"
        : "+f"(c[0]), "+f"(c[1]), "+f"(c[2]), "+f"(c[3])
        : "r"(a[0]), "r"(a[1]), "r"(a[2]), "r"(a[3]), "r"(b0), "r"(b1));
}
__device__ __forceinline__ float ex2f(float x) {
    float y;
    asm("ex2.approx.f32 %0, %1;" : "=f"(y) : "f"(x));
    return y;
}
__device__ __forceinline__ uint32_t packbf(float a, float b) {
    __nv_bfloat162 t = __floats2bfloat162_rn(a, b);
    return *(uint32_t*)&t;
}
__device__ __forceinline__ uint32_t packh(float a, float b) {
    __half2 t = __floats2half2_rn(a, b);
    return *(uint32_t*)&t;
}
__device__ __forceinline__ void packsplit(float x, float y,
                                          uint32_t& h, uint32_t& l) {
    const __nv_bfloat16 hx = __float2bfloat16_rn(x);
    const __nv_bfloat16 hy = __float2bfloat16_rn(y);
    __nv_bfloat162 hp; hp.x = hx; hp.y = hy;
    h = *(uint32_t*)&hp;
    l = packbf(x - __bfloat162float(hx), y - __bfloat162float(hy));
}
__device__ __forceinline__ void splits(float v, __nv_bfloat16& h,
                                       __nv_bfloat16& l) {
    h = __float2bfloat16_rn(v);
    l = __float2bfloat16_rn(v - __bfloat162float(h));
}
__device__ __forceinline__ void cp16(uint32_t dst, const void* src) {
    asm volatile("cp.async.cg.shared.global [%0], [%1], 16;"
                 :: "r"(dst), "l"(src) : "memory");
}
__device__ __forceinline__ void cp_commit() {
    asm volatile("cp.async.commit_group;" ::: "memory");
}
__device__ __forceinline__ void cp_wait1() {
    asm volatile("cp.async.wait_group 1;" ::: "memory");
}
__device__ __forceinline__ void cp_wait0() {
    asm volatile("cp.async.wait_group 0;" ::: "memory");
}

// ---------------------------------------------------------------------------
// xsplit: x -> g_xs (bf16 2-term chunked) AND g_xh (fp16 single)
// ---------------------------------------------------------------------------
__global__ void xsplit_kernel(const float* __restrict__ x)
{
    const int t   = blockIdx.x * 256 + threadIdx.x;
    const int row = t / 192;
    const int k0  = (t % 192) * 4;
    const float4 a = *(const float4*)(x + (size_t)row * CD + k0);
    uint32_t h0, l0, h1, l1;
    packsplit(a.x, a.y, h0, l0);
    packsplit(a.z, a.w, h1, l1);
    const size_t d = (size_t)row * CD2 + (k0 >> 4) * 32 + (k0 & 15);
    *(uint2*)(g_xs + d)      = make_uint2(h0, h1);
    *(uint2*)(g_xs + d + 16) = make_uint2(l0, l1);
    *(uint2*)(g_xh + (size_t)row * CD + k0) =
        make_uint2(packh(a.x, a.y), packh(a.z, a.w));
}

// ---------------------------------------------------------------------------
// wsplit: slots 0,1 -> g_wt bf16 2-term; slot 2 -> g_wtv fp16; slot 3 -> g_wto
// ---------------------------------------------------------------------------
__global__ void wsplit_kernel(const float* __restrict__ W0,
                              const float* __restrict__ W1,
                              const float* __restrict__ W2,
                              const float* __restrict__ W3)
{
    const int slot = blockIdx.z;
    const float* __restrict__ W = (slot == 0) ? W0 : (slot == 1) ? W1
                                : (slot == 2) ? W2 : W3;
    __shared__ float t[32][33];
    const int n0 = blockIdx.x * 32;
    const int k0 = blockIdx.y * 32;
    const int tx = threadIdx.x;
    const int ty = threadIdx.y;
#pragma unroll
    for (int i = 0; i < 32; i += 8)
        t[ty + i][tx] = W[(k0 + ty + i) * CD + n0 + tx];
    __syncthreads();
#pragma unroll
    for (int i = 0; i < 32; i += 8) {
        const float v = t[tx][ty + i];
        const int k = k0 + tx, n = n0 + ty + i;
        const size_t idx = (size_t)n * CD2 + (k >> 4) * 32 + (k & 15);
        if (slot <= 1) {
            __nv_bfloat16 h, l;
            splits(v, h, l);
            __nv_bfloat16* dst = g_wt + (size_t)slot * CD * CD2;
            dst[idx]      = h;
            dst[idx + 16] = l;
        } else {
            __half* dst = (slot == 2) ? g_wtv : g_wto;
            const __half h = __float2half_rn(v);
            const __half l = __float2half_rn(v - __half2float(h));
            dst[idx]      = h;
            dst[idx + 16] = l;
        }
    }
}

// ---------------------------------------------------------------------------
// Fused QKV GEMM (3-stage cp.async).  slot 0 output scaled by log2e.
// (R13 ordering — R14's term-major was neutral.)
// ---------------------------------------------------------------------------
constexpr int GSB = 128 * 80;
constexpr int QKV_SMEM = 6 * GSB;

__global__ void __launch_bounds__(256, 2)
gemm_qkv(const float* __restrict__ bq, const float* __restrict__ bk,
         const float* __restrict__ bv)
{
    const int slot = blockIdx.z;
    const char* __restrict__ Bgc = (slot == 2) ? (const char*)g_wtv
                 : (const char*)(g_wt + (size_t)slot * CD * CD2);
    const float* __restrict__ bias = (slot == 0) ? bq : (slot == 1) ? bk : bv;

    extern __shared__ __align__(16) char dsm[];
    const uint32_t as_b = smem_u32(dsm);
    const uint32_t bs_b = as_b + 3 * GSB;

    const int tid  = threadIdx.x;
    const int wid  = tid >> 5;
    const int lane = tid & 31;
    const int n0   = blockIdx.x * 128;
    const int m0   = blockIdx.y * 128;
    const int wm   = wid & 3;
    const int wn   = wid >> 2;

    const uint32_t b_base = bs_b + (wn * 64 + (lane & 7) + ((lane >> 4) << 3)) * 80
                          + ((lane >> 3) & 1) * 16;

    float c[2][8][4];
#pragma unroll
    for (int mi = 0; mi < 2; ++mi)
#pragma unroll
        for (int nf = 0; nf < 8; ++nf)
#pragma unroll
            for (int q = 0; q < 4; ++q) c[mi][nf][q] = 0.f;

    if (slot <= 1) {
        const uint32_t a_base = as_b + (wm * 32 + (lane & 15)) * 80
                              + (lane >> 4) * 16;
        const int srow = tid >> 2;
        const int sj   = (tid & 3) * 16;

        auto issue = [&](int kc, int s) {
#pragma unroll
            for (int u = 0; u < 2; ++u) {
                const int row = srow + 64 * u;
                cp16(as_b + s * GSB + row * 80 + sj,
                     (const char*)g_xs + (size_t)(m0 + row) * 3072 + kc * 64 + sj);
                cp16(bs_b + s * GSB + row * 80 + sj,
                     Bgc + (size_t)(n0 + row) * 3072 + kc * 64 + sj);
            }
            cp_commit();
        };

        issue(0, 0);
        issue(1, 1);

        for (int kc = 0; kc < 48; ++kc) {
            if (kc < 47) cp_wait1(); else cp_wait0();
            __syncthreads();
            if (kc + 2 < 48) issue(kc + 2, (kc + 2) % 3);
            const uint32_t sb = (kc % 3) * GSB;

            uint32_t ah[2][4], al[2][4];
#pragma unroll
            for (int mi = 0; mi < 2; ++mi) {
                const uint32_t aa = a_base + sb + mi * 16 * 80;
                ldsm_x4(ah[mi][0], ah[mi][1], ah[mi][2], ah[mi][3], aa);
                ldsm_x4(al[mi][0], al[mi][1], al[mi][2], al[mi][3], aa + 32);
            }
#pragma unroll
            for (int nj = 0; nj < 4; ++nj) {
                const uint32_t bb = b_base + sb + nj * 16 * 80;
                uint32_t bh0, bh1, bh2, bh3, bl0, bl1, bl2, bl3;
                ldsm_x4(bh0, bh1, bh2, bh3, bb);
                ldsm_x4(bl0, bl1, bl2, bl3, bb + 32);
#pragma unroll
                for (int mi = 0; mi < 2; ++mi) {
                    float* c0 = c[mi][nj * 2];
                    float* c1 = c[mi][nj * 2 + 1];
                    mma16816(c0, ah[mi], bh0, bh1);
                    mma16816(c0, al[mi], bh0, bh1);
                    mma16816(c0, ah[mi], bl0, bl1);
                    mma16816(c1, ah[mi], bh2, bh3);
                    mma16816(c1, al[mi], bh2, bh3);
                    mma16816(c1, ah[mi], bl2, bl3);
                }
            }
        }
    } else {
        const uint32_t a_base = as_b + (wm * 32 + (lane & 15)) * 48
                              + (lane >> 4) * 16;
        const int arow = tid >> 1;
        const int aj   = (tid & 1) * 16;
        const int srow = tid >> 2;
        const int sj   = (tid & 3) * 16;

        auto issue = [&](int kc, int s) {
            cp16(as_b + s * GSB + arow * 48 + aj,
                 (const char*)g_xh + (size_t)(m0 + arow) * 1536 + kc * 32 + aj);
#pragma unroll
            for (int u = 0; u < 2; ++u) {
                const int row = srow + 64 * u;
                cp16(bs_b + s * GSB + row * 80 + sj,
                     Bgc + (size_t)(n0 + row) * 3072 + kc * 64 + sj);
            }
            cp_commit();
        };

        issue(0, 0);
        issue(1, 1);

        for (int kc = 0; kc < 48; ++kc) {
            if (kc < 47) cp_wait1(); else cp_wait0();
            __syncthreads();
            if (kc + 2 < 48) issue(kc + 2, (kc + 2) % 3);
            const uint32_t sb = (kc % 3) * GSB;

            uint32_t ah[2][4];
#pragma unroll
            for (int mi = 0; mi < 2; ++mi) {
                const uint32_t aa = a_base + sb + mi * 16 * 48;
                ldsm_x4(ah[mi][0], ah[mi][1], ah[mi][2], ah[mi][3], aa);
            }
#pragma unroll
            for (int nj = 0; nj < 4; ++nj) {
                const uint32_t bb = b_base + sb + nj * 16 * 80;
                uint32_t bh0, bh1, bh2, bh3, bl0, bl1, bl2, bl3;
                ldsm_x4(bh0, bh1, bh2, bh3, bb);
                ldsm_x4(bl0, bl1, bl2, bl3, bb + 32);
#pragma unroll
                for (int mi = 0; mi < 2; ++mi) {
                    float* c0 = c[mi][nj * 2];
                    float* c1 = c[mi][nj * 2 + 1];
                    mma16816h(c0, ah[mi], bh0, bh1);
                    mma16816h(c0, ah[mi], bl0, bl1);
                    mma16816h(c1, ah[mi], bh2, bh3);
                    mma16816h(c1, ah[mi], bl2, bl3);
                }
            }
        }
    }

    // ---- epilogue ----
    const float qscale = (slot == 0) ? 1.4426950408889634f : 1.0f;  // log2e
#pragma unroll
    for (int mi = 0; mi < 2; ++mi) {
        const int r = m0 + wm * 32 + mi * 16 + (lane >> 2);
#pragma unroll
        for (int nf = 0; nf < 8; ++nf) {
            const int col = wn * 64 + nf * 8 + 2 * (lane & 3) + n0;
            const float b0 = bias[col], b1 = bias[col + 1];
            const float2 v0 = make_float2((c[mi][nf][0] + b0) * qscale,
                                          (c[mi][nf][1] + b1) * qscale);
            const float2 v1 = make_float2((c[mi][nf][2] + b0) * qscale,
                                          (c[mi][nf][3] + b1) * qscale);
            const int b = r >> 10;
            const int n = r & (CN - 1);
            const int h = col >> 6;
            if (slot <= 1) {
                __nv_bfloat16* dh = (slot == 0) ? g_qh : g_kh;
                __nv_bfloat16* dl = (slot == 0) ? g_ql : g_kl;
                uint32_t h0, l0, h1, l1;
                packsplit(v0.x, v0.y, h0, l0);
                packsplit(v1.x, v1.y, h1, l1);
                const size_t i0 = ((size_t)(b * CH + h) * CN + n) * CHD + (col & 63);
                *(uint32_t*)(dh + i0)           = h0;
                *(uint32_t*)(dl + i0)           = l0;
                *(uint32_t*)(dh + i0 + 8 * CHD) = h1;
                *(uint32_t*)(dl + i0 + 8 * CHD) = l1;
            } else {
                const size_t base = ((size_t)(b * CH + h) * CHD + (col & 63)) * CN + n;
                g_vt[base]          = __float2half_rn(v0.x);
                g_vt[base + CN]     = __float2half_rn(v0.y);
                g_vt[base + 8]      = __float2half_rn(v1.x);
                g_vt[base + CN + 8] = __float2half_rn(v1.y);
            }
        }
    }
}

// ---------------------------------------------------------------------------
// Output GEMM (unchanged from R13): g_ash fp16 @ Wo fp16 2-term + bo.
// ---------------------------------------------------------------------------
constexpr int OAB = 64 * 48;
constexpr int OBB = 128 * 80;

__global__ void __launch_bounds__(256, 2)
gemm_o(const float* __restrict__ bias, float* __restrict__ O)
{
    __shared__ __align__(16) char As[3 * OAB];
    __shared__ __align__(16) char Bs[3 * OBB];

    const int tid  = threadIdx.x;
    const int wid  = tid >> 5;
    const int lane = tid & 31;
    const int n0   = blockIdx.x * 128;
    const int m0   = blockIdx.y * 64;
    const int wm   = wid & 1;
    const int wn   = wid >> 1;

    const uint32_t as_b = smem_u32(As);
    const uint32_t bs_b = smem_u32(Bs);
    const uint32_t a_base = as_b + (wm * 32 + (lane & 15)) * 48 + (lane >> 4) * 16;
    const uint32_t b_base = bs_b + (wn * 32 + (lane & 7) + ((lane >> 4) << 3)) * 80
                          + ((lane >> 3) & 1) * 16;

    auto issue = [&](int kc, int s) {
        if (tid < 128) {
            const int row = tid >> 1, j = (tid & 1) * 16;
            cp16(as_b + s * OAB + row * 48 + j,
                 (const char*)g_ash + (size_t)(m0 + row) * 1536 + kc * 32 + j);
        }
#pragma unroll
        for (int u = 0; u < 2; ++u) {
            const int e = tid + 256 * u;
            const int row = e >> 2, sj = (e & 3) * 16;
            cp16(bs_b + s * OBB + row * 80 + sj,
                 (const char*)g_wto + (size_t)(n0 + row) * 3072 + kc * 64 + sj);
        }
        cp_commit();
    };

    float c[2][4][4];
#pragma unroll
    for (int mi = 0; mi < 2; ++mi)
#pragma unroll
        for (int nf = 0; nf < 4; ++nf)
#pragma unroll
            for (int q = 0; q < 4; ++q) c[mi][nf][q] = 0.f;

    issue(0, 0);
    issue(1, 1);

    for (int kc = 0; kc < 48; ++kc) {
        if (kc < 47) cp_wait1(); else cp_wait0();
        __syncthreads();
        if (kc + 2 < 48) issue(kc + 2, (kc + 2) % 3);
        const uint32_t sa  = (kc % 3) * OAB;
        const uint32_t sbb = (kc % 3) * OBB;

        uint32_t ah[2][4];
#pragma unroll
        for (int mi = 0; mi < 2; ++mi) {
            const uint32_t aa = a_base + sa + mi * 16 * 48;
            ldsm_x4(ah[mi][0], ah[mi][1], ah[mi][2], ah[mi][3], aa);
        }
#pragma unroll
        for (int nj = 0; nj < 2; ++nj) {
            const uint32_t bb = b_base + sbb + nj * 16 * 80;
            uint32_t bh0, bh1, bh2, bh3, bl0, bl1, bl2, bl3;
            ldsm_x4(bh0, bh1, bh2, bh3, bb);
            ldsm_x4(bl0, bl1, bl2, bl3, bb + 32);
#pragma unroll
            for (int mi = 0; mi < 2; ++mi) {
                float* c0 = c[mi][nj * 2];
                float* c1 = c[mi][nj * 2 + 1];
                mma16816h(c0, ah[mi], bh0, bh1);
                mma16816h(c0, ah[mi], bl0, bl1);
                mma16816h(c1, ah[mi], bh2, bh3);
                mma16816h(c1, ah[mi], bl2, bl3);
            }
        }
    }

#pragma unroll
    for (int mi = 0; mi < 2; ++mi) {
        const int r = m0 + wm * 32 + mi * 16 + (lane >> 2);
#pragma unroll
        for (int nf = 0; nf < 4; ++nf) {
            const int col = n0 + wn * 32 + nf * 8 + 2 * (lane & 3);
            const float b0 = bias[col], b1 = bias[col + 1];
            *(float2*)(O + (size_t)r * CD + col) =
                make_float2(c[mi][nf][0] + b0, c[mi][nf][1] + b1);
            *(float2*)(O + (size_t)(r + 8) * CD + col) =
                make_float2(c[mi][nf][2] + b0, c[mi][nf][3] + b1);
        }
    }
}

// ---------------------------------------------------------------------------
// Flash attention R15: R13 tile/math, but 3-STAGE K/V cp.async with ONE
// barrier per tile and prefetch issued immediately after the barrier.
// smem: Q [0,34816) | K 3x17408 | V 3x9216 = 114688 B.
// ---------------------------------------------------------------------------
constexpr int QSB  = 128 * 272;             // 34816
constexpr int KSB2 = 64 * 272;              // 17408
constexpr int VSBH = 64 * 144;              // 9216
constexpr int ATT_SMEM = QSB + 3 * (KSB2 + VSBH);  // 114688

__global__ void __launch_bounds__(256, 2)
attn_mma_kernel()
{
    extern __shared__ __align__(16) char dsm[];
    const uint32_t qs_b = smem_u32(dsm);
    const uint32_t ks_b = qs_b + QSB;
    const uint32_t vs_b = ks_b + 3 * KSB2;

    const int tid  = threadIdx.x;
    const int w    = tid >> 5;
    const int lane = tid & 31;
    const int wm   = w & 3;
    const int wk   = w >> 2;
    const int bh   = blockIdx.y;
    const int q0   = blockIdx.x * 128;
    const int r0   = lane >> 2;
    const int cc   = (lane & 3) * 2;

    const uint32_t a_base = qs_b + (wm * 32 + (lane & 15)) * 272 + (lane >> 4) * 16;
    const uint32_t kfrag  = ks_b + (wk * 32 + (lane & 7) + ((lane >> 4) << 3)) * 272
                          + ((lane >> 3) & 1) * 16;
    const uint32_t vfrag  = vs_b + ((lane & 7) + ((lane >> 4) << 3)) * 144
                          + ((lane >> 3) & 1) * 16 + wk * 64;
    const size_t qbase = ((size_t)bh * CN + q0) * CHD;
    const size_t kbase = (size_t)bh * CN * CHD;
    const size_t vbase = (size_t)bh * CHD * CN;

    auto issueKV = [&](int kt, int s) {
#pragma unroll
        for (int u = 0; u < 4; ++u) {
            const int e = tid + 256 * u;
            const int row = e >> 4, j = e & 15;
            const __nv_bfloat16* src = (j < 8 ? g_kh : g_kl) + kbase
                                     + (size_t)(kt * 64 + row) * CHD + (j & 7) * 8;
            cp16(ks_b + s * KSB2 + row * 272 + j * 16, src);
        }
#pragma unroll
        for (int u = 0; u < 2; ++u) {
            const int e = tid + 256 * u;
            const int row = e >> 3, j = e & 7;
            const __half* src = g_vt + vbase + (size_t)row * CN + kt * 64 + j * 8;
            cp16(vs_b + s * VSBH + row * 144 + j * 16, src);
        }
        cp_commit();
    };

    float oc[2][8][4];
#pragma unroll
    for (int mi = 0; mi < 2; ++mi)
#pragma unroll
        for (int f = 0; f < 8; ++f)
#pragma unroll
            for (int q = 0; q < 4; ++q) oc[mi][f][q] = 0.f;
    float mrow[2][2] = {{-1e30f, -1e30f}, {-1e30f, -1e30f}};
    float lrow[2][2] = {{0.f, 0.f}, {0.f, 0.f}};

    // ---- prologue: Q (group 0) + KV stages 0,1 ----
#pragma unroll
    for (int u = 0; u < 8; ++u) {
        const int e = tid + 256 * u;
        const int row = e >> 4, j = e & 15;
        const __nv_bfloat16* src = (j < 8 ? g_qh : g_ql) + qbase
                                 + (size_t)row * CHD + (j & 7) * 8;
        cp16(qs_b + row * 272 + j * 16, src);
    }
    issueKV(0, 0);   // group 0 = {Q, K0, V0}
    issueKV(1, 1);   // group 1

    for (int kt = 0; kt < 16; ++kt) {
        if (kt < 15) cp_wait1(); else cp_wait0();
        __syncthreads();
        if (kt + 2 < 16) issueKV(kt + 2, (kt + 2) % 3);
        const uint32_t sK = (kt % 3) * KSB2;
        const uint32_t sV = (kt % 3) * VSBH;

        // ---- S = Q K^T : bf16 3-term ----
        float sc[2][4][4];
#pragma unroll
        for (int mi = 0; mi < 2; ++mi)
#pragma unroll
            for (int f = 0; f < 4; ++f)
#pragma unroll
                for (int q = 0; q < 4; ++q) sc[mi][f][q] = 0.f;
#pragma unroll
        for (int ks = 0; ks < 4; ++ks) {
            uint32_t qhf[2][4], qlf[2][4];
#pragma unroll
            for (int mi = 0; mi < 2; ++mi) {
                const uint32_t aa = a_base + mi * 16 * 272 + ks * 32;
                ldsm_x4(qhf[mi][0], qhf[mi][1], qhf[mi][2], qhf[mi][3], aa);
                ldsm_x4(qlf[mi][0], qlf[mi][1], qlf[mi][2], qlf[mi][3], aa + 128);
            }
#pragma unroll
            for (int nj = 0; nj < 2; ++nj) {
                const uint32_t bb = kfrag + sK + nj * 16 * 272 + ks * 32;
                uint32_t kh0, kh1, kh2, kh3, kl0, kl1, kl2, kl3;
                ldsm_x4(kh0, kh1, kh2, kh3, bb);
                ldsm_x4(kl0, kl1, kl2, kl3, bb + 128);
#pragma unroll
                for (int mi = 0; mi < 2; ++mi) {
                    float* s0 = sc[mi][nj * 2];
                    float* s1 = sc[mi][nj * 2 + 1];
                    mma16816(s0, qhf[mi], kh0, kh1);
                    mma16816(s0, qlf[mi], kh0, kh1);
                    mma16816(s0, qhf[mi], kl0, kl1);
                    mma16816(s1, qhf[mi], kh2, kh3);
                    mma16816(s1, qlf[mi], kh2, kh3);
                    mma16816(s1, qhf[mi], kl2, kl3);
                }
            }
        }

        // ---- online-max softmax, log2 domain, rescale skip ----
#pragma unroll
        for (int mi = 0; mi < 2; ++mi) {
            float mt0 = -1e30f, mt1 = -1e30f;
#pragma unroll
            for (int f = 0; f < 4; ++f) {
                mt0 = fmaxf(mt0, fmaxf(sc[mi][f][0], sc[mi][f][1]));
                mt1 = fmaxf(mt1, fmaxf(sc[mi][f][2], sc[mi][f][3]));
            }
            mt0 = fmaxf(mt0, __shfl_xor_sync(0xffffffffu, mt0, 1));
            mt0 = fmaxf(mt0, __shfl_xor_sync(0xffffffffu, mt0, 2));
            mt1 = fmaxf(mt1, __shfl_xor_sync(0xffffffffu, mt1, 1));
            mt1 = fmaxf(mt1, __shfl_xor_sync(0xffffffffu, mt1, 2));

            const bool upd = __any_sync(0xffffffffu,
                (mt0 > mrow[mi][0]) || (mt1 > mrow[mi][1]));
            float mn0 = mrow[mi][0], mn1 = mrow[mi][1];
            if (upd) {
                mn0 = fmaxf(mrow[mi][0], mt0);
                mn1 = fmaxf(mrow[mi][1], mt1);
                const float e0 = ex2f(mrow[mi][0] - mn0);
                const float e1 = ex2f(mrow[mi][1] - mn1);
                mrow[mi][0] = mn0; mrow[mi][1] = mn1;
                lrow[mi][0] *= e0; lrow[mi][1] *= e1;
#pragma unroll
                for (int f = 0; f < 8; ++f) {
                    oc[mi][f][0] *= e0; oc[mi][f][1] *= e0;
                    oc[mi][f][2] *= e1; oc[mi][f][3] *= e1;
                }
            }
            float rs0 = 0.f, rs1 = 0.f;
#pragma unroll
            for (int f = 0; f < 4; ++f) {
                sc[mi][f][0] = ex2f(sc[mi][f][0] - mn0); rs0 += sc[mi][f][0];
                sc[mi][f][1] = ex2f(sc[mi][f][1] - mn0); rs0 += sc[mi][f][1];
                sc[mi][f][2] = ex2f(sc[mi][f][2] - mn1); rs1 += sc[mi][f][2];
                sc[mi][f][3] = ex2f(sc[mi][f][3] - mn1); rs1 += sc[mi][f][3];
            }
            lrow[mi][0] += rs0; lrow[mi][1] += rs1;
        }

        // ---- O += P V : fp16 single ----
#pragma unroll
        for (int ks = 0; ks < 2; ++ks) {
            uint32_t ph[2][4];
#pragma unroll
            for (int mi = 0; mi < 2; ++mi) {
                ph[mi][0] = packh(sc[mi][2 * ks][0],     sc[mi][2 * ks][1]);
                ph[mi][1] = packh(sc[mi][2 * ks][2],     sc[mi][2 * ks][3]);
                ph[mi][2] = packh(sc[mi][2 * ks + 1][0], sc[mi][2 * ks + 1][1]);
                ph[mi][3] = packh(sc[mi][2 * ks + 1][2], sc[mi][2 * ks + 1][3]);
            }
#pragma unroll
            for (int nj = 0; nj < 4; ++nj) {
                const uint32_t bb = vfrag + sV + nj * 16 * 144 + ks * 32;
                uint32_t vh0, vh1, vh2, vh3;
                ldsm_x4(vh0, vh1, vh2, vh3, bb);
#pragma unroll
                for (int mi = 0; mi < 2; ++mi) {
                    mma16816h(oc[mi][nj * 2],     ph[mi], vh0, vh1);
                    mma16816h(oc[mi][nj * 2 + 1], ph[mi], vh2, vh3);
                }
            }
        }
    }

    // ---- quad-reduce partial l ----
#pragma unroll
    for (int mi = 0; mi < 2; ++mi)
#pragma unroll
        for (int r = 0; r < 2; ++r) {
            lrow[mi][r] += __shfl_xor_sync(0xffffffffu, lrow[mi][r], 1);
            lrow[mi][r] += __shfl_xor_sync(0xffffffffu, lrow[mi][r], 2);
        }

    // ---- cross-key-group merge with max rescale (log2 domain) ----
    float* red = (float*)dsm + (wm * 32 + lane) * 72;
    __syncthreads();
    if (wk == 1) {
#pragma unroll
        for (int mi = 0; mi < 2; ++mi)
#pragma unroll
            for (int f = 0; f < 8; ++f)
#pragma unroll
                for (int q = 0; q < 4; ++q)
                    red[mi * 32 + f * 4 + q] = oc[mi][f][q];
        red[64] = lrow[0][0]; red[65] = lrow[0][1];
        red[66] = lrow[1][0]; red[67] = lrow[1][1];
        red[68] = mrow[0][0]; red[69] = mrow[0][1];
        red[70] = mrow[1][0]; red[71] = mrow[1][1];
    }
    __syncthreads();
    if (wk == 1) return;

#pragma unroll
    for (int mi = 0; mi < 2; ++mi)
#pragma unroll
        for (int rh = 0; rh < 2; ++rh) {
            const float mB = red[68 + mi * 2 + rh];
            const float lB = red[64 + mi * 2 + rh];
            const float mM = fmaxf(mrow[mi][rh], mB);
            const float sA = ex2f(mrow[mi][rh] - mM);
            const float sB = ex2f(mB - mM);
            lrow[mi][rh] = lrow[mi][rh] * sA + lB * sB;
#pragma unroll
            for (int f = 0; f < 8; ++f)
#pragma unroll
                for (int q = rh * 2; q < rh * 2 + 2; ++q)
                    oc[mi][f][q] = oc[mi][f][q] * sA
                                 + red[mi * 32 + f * 4 + q] * sB;
        }

    // ---- epilogue: normalize + post-scale -> fp16 single g_ash ----
    const float post = 0.03608439182435161f;   // 1/sqrt(768)
    const int b = bh / CH;
    const int h = bh % CH;
#pragma unroll
    for (int mi = 0; mi < 2; ++mi) {
        const float f0 = post / lrow[mi][0];
        const float f1 = post / lrow[mi][1];
        const size_t R0 = (size_t)(b * CN + q0 + wm * 32 + mi * 16 + r0);
#pragma unroll
        for (int j = 0; j < 8; ++j) {
            const int c = h * 64 + 8 * j + cc;
            *(uint32_t*)(g_ash + R0 * CD + c) =
                packh(oc[mi][j][0] * f0, oc[mi][j][1] * f0);
            *(uint32_t*)(g_ash + (R0 + 8) * CD + c) =
                packh(oc[mi][j][2] * f1, oc[mi][j][3] * f1);
        }
    }
}

// ---------------------------------------------------------------------------
extern "C" void kernel_launch(void* const* d_in, const int* in_sizes, int n_in,
                              void* d_out, int out_size)
{
    (void)in_sizes; (void)n_in; (void)out_size;
    const float* x  = (const float*)d_in[0];
    const float* Wq = (const float*)d_in[1];
    const float* bq = (const float*)d_in[2];
    const float* Wk = (const float*)d_in[3];
    const float* bk = (const float*)d_in[4];
    const float* Wv = (const float*)d_in[5];
    const float* bv = (const float*)d_in[6];
    const float* Wo = (const float*)d_in[7];
    const float* bo = (const float*)d_in[8];
    float* out = (float*)d_out;

    cudaFuncSetAttribute(gemm_qkv,
                         cudaFuncAttributeMaxDynamicSharedMemorySize, QKV_SMEM);
    cudaFuncSetAttribute(attn_mma_kernel,
                         cudaFuncAttributeMaxDynamicSharedMemorySize, ATT_SMEM);

    xsplit_kernel<<<CM * (CD / 4) / 256, 256>>>(x);
    wsplit_kernel<<<dim3(24, 24, 4), dim3(32, 8)>>>(Wq, Wk, Wv, Wo);
    gemm_qkv<<<dim3(6, 64, 3), 256, QKV_SMEM>>>(bq, bk, bv);
    attn_mma_kernel<<<dim3(CN / 128, BH), 256, ATT_SMEM>>>();
    gemm_o<<<dim3(6, 128), 256>>>(bo, out);
}

// round 16
// speedup vs baseline: 1.0354x; 1.0354x over previous
#include <cuda_runtime.h>
#include <cuda_bf16.h>
#include <cuda_fp16.h>
#include <cstdint>

// ---------------------------------------------------------------------------
// MHSA: B=8, N=1024, D=768, H=12, HD=64.
// R16 = R15 (3-stage attn, best attn 179.9us) + FUSED PREP: xsplit + wsplit
// combined into ONE launch (independent work, block-uniform branch) to remove
// a serial launch and overlap their DRAM traffic.  No math changes:
// rel_err must be exactly 3.413968e-4.
// ---------------------------------------------------------------------------

constexpr int CB  = 8;
constexpr int CN  = 1024;
constexpr int CD  = 768;
constexpr int CH  = 12;
constexpr int CHD = 64;
constexpr int CM  = CB * CN;   // 8192
constexpr int BH  = CB * CH;   // 96
constexpr int CD2 = CD * 2;

__device__ __nv_bfloat16 g_qh[BH * CN * CHD], g_ql[BH * CN * CHD];
__device__ __nv_bfloat16 g_kh[BH * CN * CHD], g_kl[BH * CN * CHD];
__device__ __half        g_vt[BH * CHD * CN];
__device__ __nv_bfloat16 g_xs[CM * CD2];
__device__ __half        g_xh[CM * CD];
__device__ __half        g_ash[CM * CD];
__device__ __nv_bfloat16 g_wt[2 * CD * CD2];
__device__ __half        g_wtv[CD * CD2];
__device__ __half        g_wto[CD * CD2];

// ======================= PTX helpers =======================================
__device__ __forceinline__ uint32_t smem_u32(const void* p) {
    uint32_t a;
    asm("{ .reg .u64 t; cvta.to.shared.u64 t, %1; cvt.u32.u64 %0, t; }"
        : "=r"(a) : "l"(p));
    return a;
}
__device__ __forceinline__ void ldsm_x4(uint32_t& r0, uint32_t& r1,
                                        uint32_t& r2, uint32_t& r3,
                                        uint32_t addr) {
    asm volatile("ldmatrix.sync.aligned.m8n8.x4.shared.b16 {%0,%1,%2,%3}, [%4];"
                 : "=r"(r0), "=r"(r1), "=r"(r2), "=r"(r3) : "r"(addr));
}
__device__ __forceinline__ void mma16816(float* c, const uint32_t* a,
                                         uint32_t b0, uint32_t b1) {
    asm volatile(
        "mma.sync.aligned.m16n8k16.row.col.f32.bf16.bf16.f32 "
        "{%0,%1,%2,%3}, {%4,%5,%6,%7}, {%8,%9}, {%0,%1,%2,%3};"
        : "+f"(c[0]), "+f"(c[1]), "+f"(c[2]), "+f"(c[3])
        : "r"(a[0]), "r"(a[1]), "r"(a[2]), "r"(a[3]), "r"(b0), "r"(b1));
}
__device__ __forceinline__ void mma16816h(float* c, const uint32_t* a,
                                          uint32_t b0, uint32_t b1) {
    asm volatile(
        "mma.sync.aligned.m16n8k16.row.col.f32.f16.f16.f32 "
        "{%0,%1,%2,%3}, {%4,%5,%6,%7}, {%8,%9}, {%0,%1,%2,%3};"
        : "+f"(c[0]), "+f"(c[1]), "+f"(c[2]), "+f"(c[3])
        : "r"(a[0]), "r"(a[1]), "r"(a[2]), "r"(a[3]), "r"(b0), "r"(b1));
}
__device__ __forceinline__ float ex2f(float x) {
    float y;
    asm("ex2.approx.f32 %0, %1;" : "=f"(y) : "f"(x));
    return y;
}
__device__ __forceinline__ uint32_t packbf(float a, float b) {
    __nv_bfloat162 t = __floats2bfloat162_rn(a, b);
    return *(uint32_t*)&t;
}
__device__ __forceinline__ uint32_t packh(float a, float b) {
    __half2 t = __floats2half2_rn(a, b);
    return *(uint32_t*)&t;
}
__device__ __forceinline__ void packsplit(float x, float y,
                                          uint32_t& h, uint32_t& l) {
    const __nv_bfloat16 hx = __float2bfloat16_rn(x);
    const __nv_bfloat16 hy = __float2bfloat16_rn(y);
    __nv_bfloat162 hp; hp.x = hx; hp.y = hy;
    h = *(uint32_t*)&hp;
    l = packbf(x - __bfloat162float(hx), y - __bfloat162float(hy));
}
__device__ __forceinline__ void splits(float v, __nv_bfloat16& h,
                                       __nv_bfloat16& l) {
    h = __float2bfloat16_rn(v);
    l = __float2bfloat16_rn(v - __bfloat162float(h));
}
__device__ __forceinline__ void cp16(uint32_t dst, const void* src) {
    asm volatile("cp.async.cg.shared.global [%0], [%1], 16;"
                 :: "r"(dst), "l"(src) : "memory");
}
__device__ __forceinline__ void cp_commit() {
    asm volatile("cp.async.commit_group;" ::: "memory");
}
__device__ __forceinline__ void cp_wait1() {
    asm volatile("cp.async.wait_group 1;" ::: "memory");
}
__device__ __forceinline__ void cp_wait0() {
    asm volatile("cp.async.wait_group 0;" ::: "memory");
}

// ---------------------------------------------------------------------------
// FUSED prep: blocks [0, 2304) = wsplit (slot = bx/576), blocks [2304, 8448)
// = xsplit.  Branch is block-uniform, so the barrier in the wsplit arm is
// safe.  Bodies identical to R15's separate kernels.
// ---------------------------------------------------------------------------
constexpr int WSPLIT_BLOCKS = 24 * 24 * 4;          // 2304
constexpr int XSPLIT_BLOCKS = CM * (CD / 4) / 256;  // 6144
constexpr int PREP_BLOCKS   = WSPLIT_BLOCKS + XSPLIT_BLOCKS;

__global__ void prep_kernel(const float* __restrict__ x,
                            const float* __restrict__ W0,
                            const float* __restrict__ W1,
                            const float* __restrict__ W2,
                            const float* __restrict__ W3)
{
    __shared__ float t[32][33];
    const int bx  = blockIdx.x;
    const int tid = threadIdx.x;

    if (bx < WSPLIT_BLOCKS) {
        // ---- wsplit ----
        const int slot = bx / 576;
        const int r    = bx % 576;
        const int n0   = (r % 24) * 32;
        const int k0   = (r / 24) * 32;
        const int tx   = tid & 31;
        const int ty   = tid >> 5;
        const float* __restrict__ W = (slot == 0) ? W0 : (slot == 1) ? W1
                                    : (slot == 2) ? W2 : W3;
#pragma unroll
        for (int i = 0; i < 32; i += 8)
            t[ty + i][tx] = W[(k0 + ty + i) * CD + n0 + tx];
        __syncthreads();
#pragma unroll
        for (int i = 0; i < 32; i += 8) {
            const float v = t[tx][ty + i];
            const int k = k0 + tx, n = n0 + ty + i;
            const size_t idx = (size_t)n * CD2 + (k >> 4) * 32 + (k & 15);
            if (slot <= 1) {
                __nv_bfloat16 h, l;
                splits(v, h, l);
                __nv_bfloat16* dst = g_wt + (size_t)slot * CD * CD2;
                dst[idx]      = h;
                dst[idx + 16] = l;
            } else {
                __half* dst = (slot == 2) ? g_wtv : g_wto;
                const __half h = __float2half_rn(v);
                const __half l = __float2half_rn(v - __half2float(h));
                dst[idx]      = h;
                dst[idx + 16] = l;
            }
        }
    } else {
        // ---- xsplit ----
        const int e   = (bx - WSPLIT_BLOCKS) * 256 + tid;
        const int row = e / 192;
        const int k0  = (e % 192) * 4;
        const float4 a = *(const float4*)(x + (size_t)row * CD + k0);
        uint32_t h0, l0, h1, l1;
        packsplit(a.x, a.y, h0, l0);
        packsplit(a.z, a.w, h1, l1);
        const size_t d = (size_t)row * CD2 + (k0 >> 4) * 32 + (k0 & 15);
        *(uint2*)(g_xs + d)      = make_uint2(h0, h1);
        *(uint2*)(g_xs + d + 16) = make_uint2(l0, l1);
        *(uint2*)(g_xh + (size_t)row * CD + k0) =
            make_uint2(packh(a.x, a.y), packh(a.z, a.w));
    }
}

// ---------------------------------------------------------------------------
// Fused QKV GEMM (3-stage cp.async).  slot 0 output scaled by log2e.
// ---------------------------------------------------------------------------
constexpr int GSB = 128 * 80;
constexpr int QKV_SMEM = 6 * GSB;

__global__ void __launch_bounds__(256, 2)
gemm_qkv(const float* __restrict__ bq, const float* __restrict__ bk,
         const float* __restrict__ bv)
{
    const int slot = blockIdx.z;
    const char* __restrict__ Bgc = (slot == 2) ? (const char*)g_wtv
                 : (const char*)(g_wt + (size_t)slot * CD * CD2);
    const float* __restrict__ bias = (slot == 0) ? bq : (slot == 1) ? bk : bv;

    extern __shared__ __align__(16) char dsm[];
    const uint32_t as_b = smem_u32(dsm);
    const uint32_t bs_b = as_b + 3 * GSB;

    const int tid  = threadIdx.x;
    const int wid  = tid >> 5;
    const int lane = tid & 31;
    const int n0   = blockIdx.x * 128;
    const int m0   = blockIdx.y * 128;
    const int wm   = wid & 3;
    const int wn   = wid >> 2;

    const uint32_t b_base = bs_b + (wn * 64 + (lane & 7) + ((lane >> 4) << 3)) * 80
                          + ((lane >> 3) & 1) * 16;

    float c[2][8][4];
#pragma unroll
    for (int mi = 0; mi < 2; ++mi)
#pragma unroll
        for (int nf = 0; nf < 8; ++nf)
#pragma unroll
            for (int q = 0; q < 4; ++q) c[mi][nf][q] = 0.f;

    if (slot <= 1) {
        const uint32_t a_base = as_b + (wm * 32 + (lane & 15)) * 80
                              + (lane >> 4) * 16;
        const int srow = tid >> 2;
        const int sj   = (tid & 3) * 16;

        auto issue = [&](int kc, int s) {
#pragma unroll
            for (int u = 0; u < 2; ++u) {
                const int row = srow + 64 * u;
                cp16(as_b + s * GSB + row * 80 + sj,
                     (const char*)g_xs + (size_t)(m0 + row) * 3072 + kc * 64 + sj);
                cp16(bs_b + s * GSB + row * 80 + sj,
                     Bgc + (size_t)(n0 + row) * 3072 + kc * 64 + sj);
            }
            cp_commit();
        };

        issue(0, 0);
        issue(1, 1);

        for (int kc = 0; kc < 48; ++kc) {
            if (kc < 47) cp_wait1(); else cp_wait0();
            __syncthreads();
            if (kc + 2 < 48) issue(kc + 2, (kc + 2) % 3);
            const uint32_t sb = (kc % 3) * GSB;

            uint32_t ah[2][4], al[2][4];
#pragma unroll
            for (int mi = 0; mi < 2; ++mi) {
                const uint32_t aa = a_base + sb + mi * 16 * 80;
                ldsm_x4(ah[mi][0], ah[mi][1], ah[mi][2], ah[mi][3], aa);
                ldsm_x4(al[mi][0], al[mi][1], al[mi][2], al[mi][3], aa + 32);
            }
#pragma unroll
            for (int nj = 0; nj < 4; ++nj) {
                const uint32_t bb = b_base + sb + nj * 16 * 80;
                uint32_t bh0, bh1, bh2, bh3, bl0, bl1, bl2, bl3;
                ldsm_x4(bh0, bh1, bh2, bh3, bb);
                ldsm_x4(bl0, bl1, bl2, bl3, bb + 32);
#pragma unroll
                for (int mi = 0; mi < 2; ++mi) {
                    float* c0 = c[mi][nj * 2];
                    float* c1 = c[mi][nj * 2 + 1];
                    mma16816(c0, ah[mi], bh0, bh1);
                    mma16816(c0, al[mi], bh0, bh1);
                    mma16816(c0, ah[mi], bl0, bl1);
                    mma16816(c1, ah[mi], bh2, bh3);
                    mma16816(c1, al[mi], bh2, bh3);
                    mma16816(c1, ah[mi], bl2, bl3);
                }
            }
        }
    } else {
        const uint32_t a_base = as_b + (wm * 32 + (lane & 15)) * 48
                              + (lane >> 4) * 16;
        const int arow = tid >> 1;
        const int aj   = (tid & 1) * 16;
        const int srow = tid >> 2;
        const int sj   = (tid & 3) * 16;

        auto issue = [&](int kc, int s) {
            cp16(as_b + s * GSB + arow * 48 + aj,
                 (const char*)g_xh + (size_t)(m0 + arow) * 1536 + kc * 32 + aj);
#pragma unroll
            for (int u = 0; u < 2; ++u) {
                const int row = srow + 64 * u;
                cp16(bs_b + s * GSB + row * 80 + sj,
                     Bgc + (size_t)(n0 + row) * 3072 + kc * 64 + sj);
            }
            cp_commit();
        };

        issue(0, 0);
        issue(1, 1);

        for (int kc = 0; kc < 48; ++kc) {
            if (kc < 47) cp_wait1(); else cp_wait0();
            __syncthreads();
            if (kc + 2 < 48) issue(kc + 2, (kc + 2) % 3);
            const uint32_t sb = (kc % 3) * GSB;

            uint32_t ah[2][4];
#pragma unroll
            for (int mi = 0; mi < 2; ++mi) {
                const uint32_t aa = a_base + sb + mi * 16 * 48;
                ldsm_x4(ah[mi][0], ah[mi][1], ah[mi][2], ah[mi][3], aa);
            }
#pragma unroll
            for (int nj = 0; nj < 4; ++nj) {
                const uint32_t bb = b_base + sb + nj * 16 * 80;
                uint32_t bh0, bh1, bh2, bh3, bl0, bl1, bl2, bl3;
                ldsm_x4(bh0, bh1, bh2, bh3, bb);
                ldsm_x4(bl0, bl1, bl2, bl3, bb + 32);
#pragma unroll
                for (int mi = 0; mi < 2; ++mi) {
                    float* c0 = c[mi][nj * 2];
                    float* c1 = c[mi][nj * 2 + 1];
                    mma16816h(c0, ah[mi], bh0, bh1);
                    mma16816h(c0, ah[mi], bl0, bl1);
                    mma16816h(c1, ah[mi], bh2, bh3);
                    mma16816h(c1, ah[mi], bl2, bl3);
                }
            }
        }
    }

    // ---- epilogue ----
    const float qscale = (slot == 0) ? 1.4426950408889634f : 1.0f;  // log2e
#pragma unroll
    for (int mi = 0; mi < 2; ++mi) {
        const int r = m0 + wm * 32 + mi * 16 + (lane >> 2);
#pragma unroll
        for (int nf = 0; nf < 8; ++nf) {
            const int col = wn * 64 + nf * 8 + 2 * (lane & 3) + n0;
            const float b0 = bias[col], b1 = bias[col + 1];
            const float2 v0 = make_float2((c[mi][nf][0] + b0) * qscale,
                                          (c[mi][nf][1] + b1) * qscale);
            const float2 v1 = make_float2((c[mi][nf][2] + b0) * qscale,
                                          (c[mi][nf][3] + b1) * qscale);
            const int b = r >> 10;
            const int n = r & (CN - 1);
            const int h = col >> 6;
            if (slot <= 1) {
                __nv_bfloat16* dh = (slot == 0) ? g_qh : g_kh;
                __nv_bfloat16* dl = (slot == 0) ? g_ql : g_kl;
                uint32_t h0, l0, h1, l1;
                packsplit(v0.x, v0.y, h0, l0);
                packsplit(v1.x, v1.y, h1, l1);
                const size_t i0 = ((size_t)(b * CH + h) * CN + n) * CHD + (col & 63);
                *(uint32_t*)(dh + i0)           = h0;
                *(uint32_t*)(dl + i0)           = l0;
                *(uint32_t*)(dh + i0 + 8 * CHD) = h1;
                *(uint32_t*)(dl + i0 + 8 * CHD) = l1;
            } else {
                const size_t base = ((size_t)(b * CH + h) * CHD + (col & 63)) * CN + n;
                g_vt[base]          = __float2half_rn(v0.x);
                g_vt[base + CN]     = __float2half_rn(v0.y);
                g_vt[base + 8]      = __float2half_rn(v1.x);
                g_vt[base + CN + 8] = __float2half_rn(v1.y);
            }
        }
    }
}

// ---------------------------------------------------------------------------
// Output GEMM: g_ash fp16 @ Wo fp16 2-term + bo.
// ---------------------------------------------------------------------------
constexpr int OAB = 64 * 48;
constexpr int OBB = 128 * 80;

__global__ void __launch_bounds__(256, 2)
gemm_o(const float* __restrict__ bias, float* __restrict__ O)
{
    __shared__ __align__(16) char As[3 * OAB];
    __shared__ __align__(16) char Bs[3 * OBB];

    const int tid  = threadIdx.x;
    const int wid  = tid >> 5;
    const int lane = tid & 31;
    const int n0   = blockIdx.x * 128;
    const int m0   = blockIdx.y * 64;
    const int wm   = wid & 1;
    const int wn   = wid >> 1;

    const uint32_t as_b = smem_u32(As);
    const uint32_t bs_b = smem_u32(Bs);
    const uint32_t a_base = as_b + (wm * 32 + (lane & 15)) * 48 + (lane >> 4) * 16;
    const uint32_t b_base = bs_b + (wn * 32 + (lane & 7) + ((lane >> 4) << 3)) * 80
                          + ((lane >> 3) & 1) * 16;

    auto issue = [&](int kc, int s) {
        if (tid < 128) {
            const int row = tid >> 1, j = (tid & 1) * 16;
            cp16(as_b + s * OAB + row * 48 + j,
                 (const char*)g_ash + (size_t)(m0 + row) * 1536 + kc * 32 + j);
        }
#pragma unroll
        for (int u = 0; u < 2; ++u) {
            const int e = tid + 256 * u;
            const int row = e >> 2, sj = (e & 3) * 16;
            cp16(bs_b + s * OBB + row * 80 + sj,
                 (const char*)g_wto + (size_t)(n0 + row) * 3072 + kc * 64 + sj);
        }
        cp_commit();
    };

    float c[2][4][4];
#pragma unroll
    for (int mi = 0; mi < 2; ++mi)
#pragma unroll
        for (int nf = 0; nf < 4; ++nf)
#pragma unroll
            for (int q = 0; q < 4; ++q) c[mi][nf][q] = 0.f;

    issue(0, 0);
    issue(1, 1);

    for (int kc = 0; kc < 48; ++kc) {
        if (kc < 47) cp_wait1(); else cp_wait0();
        __syncthreads();
        if (kc + 2 < 48) issue(kc + 2, (kc + 2) % 3);
        const uint32_t sa  = (kc % 3) * OAB;
        const uint32_t sbb = (kc % 3) * OBB;

        uint32_t ah[2][4];
#pragma unroll
        for (int mi = 0; mi < 2; ++mi) {
            const uint32_t aa = a_base + sa + mi * 16 * 48;
            ldsm_x4(ah[mi][0], ah[mi][1], ah[mi][2], ah[mi][3], aa);
        }
#pragma unroll
        for (int nj = 0; nj < 2; ++nj) {
            const uint32_t bb = b_base + sbb + nj * 16 * 80;
            uint32_t bh0, bh1, bh2, bh3, bl0, bl1, bl2, bl3;
            ldsm_x4(bh0, bh1, bh2, bh3, bb);
            ldsm_x4(bl0, bl1, bl2, bl3, bb + 32);
#pragma unroll
            for (int mi = 0; mi < 2; ++mi) {
                float* c0 = c[mi][nj * 2];
                float* c1 = c[mi][nj * 2 + 1];
                mma16816h(c0, ah[mi], bh0, bh1);
                mma16816h(c0, ah[mi], bl0, bl1);
                mma16816h(c1, ah[mi], bh2, bh3);
                mma16816h(c1, ah[mi], bl2, bl3);
            }
        }
    }

#pragma unroll
    for (int mi = 0; mi < 2; ++mi) {
        const int r = m0 + wm * 32 + mi * 16 + (lane >> 2);
#pragma unroll
        for (int nf = 0; nf < 4; ++nf) {
            const int col = n0 + wn * 32 + nf * 8 + 2 * (lane & 3);
            const float b0 = bias[col], b1 = bias[col + 1];
            *(float2*)(O + (size_t)r * CD + col) =
                make_float2(c[mi][nf][0] + b0, c[mi][nf][1] + b1);
            *(float2*)(O + (size_t)(r + 8) * CD + col) =
                make_float2(c[mi][nf][2] + b0, c[mi][nf][3] + b1);
        }
    }
}

// ---------------------------------------------------------------------------
// Flash attention (R15): 128q CTA, 4 m-groups x 2 key-groups, 64-key tiles,
// 3-stage K/V cp.async, ONE barrier/tile, log2-domain online-max softmax,
// PV fp16 single, fp16 epilogue.
// ---------------------------------------------------------------------------
constexpr int QSB  = 128 * 272;             // 34816
constexpr int KSB2 = 64 * 272;              // 17408
constexpr int VSBH = 64 * 144;              // 9216
constexpr int ATT_SMEM = QSB + 3 * (KSB2 + VSBH);  // 114688

__global__ void __launch_bounds__(256, 2)
attn_mma_kernel()
{
    extern __shared__ __align__(16) char dsm[];
    const uint32_t qs_b = smem_u32(dsm);
    const uint32_t ks_b = qs_b + QSB;
    const uint32_t vs_b = ks_b + 3 * KSB2;

    const int tid  = threadIdx.x;
    const int w    = tid >> 5;
    const int lane = tid & 31;
    const int wm   = w & 3;
    const int wk   = w >> 2;
    const int bh   = blockIdx.y;
    const int q0   = blockIdx.x * 128;
    const int r0   = lane >> 2;
    const int cc   = (lane & 3) * 2;

    const uint32_t a_base = qs_b + (wm * 32 + (lane & 15)) * 272 + (lane >> 4) * 16;
    const uint32_t kfrag  = ks_b + (wk * 32 + (lane & 7) + ((lane >> 4) << 3)) * 272
                          + ((lane >> 3) & 1) * 16;
    const uint32_t vfrag  = vs_b + ((lane & 7) + ((lane >> 4) << 3)) * 144
                          + ((lane >> 3) & 1) * 16 + wk * 64;
    const size_t qbase = ((size_t)bh * CN + q0) * CHD;
    const size_t kbase = (size_t)bh * CN * CHD;
    const size_t vbase = (size_t)bh * CHD * CN;

    auto issueKV = [&](int kt, int s) {
#pragma unroll
        for (int u = 0; u < 4; ++u) {
            const int e = tid + 256 * u;
            const int row = e >> 4, j = e & 15;
            const __nv_bfloat16* src = (j < 8 ? g_kh : g_kl) + kbase
                                     + (size_t)(kt * 64 + row) * CHD + (j & 7) * 8;
            cp16(ks_b + s * KSB2 + row * 272 + j * 16, src);
        }
#pragma unroll
        for (int u = 0; u < 2; ++u) {
            const int e = tid + 256 * u;
            const int row = e >> 3, j = e & 7;
            const __half* src = g_vt + vbase + (size_t)row * CN + kt * 64 + j * 8;
            cp16(vs_b + s * VSBH + row * 144 + j * 16, src);
        }
        cp_commit();
    };

    float oc[2][8][4];
#pragma unroll
    for (int mi = 0; mi < 2; ++mi)
#pragma unroll
        for (int f = 0; f < 8; ++f)
#pragma unroll
            for (int q = 0; q < 4; ++q) oc[mi][f][q] = 0.f;
    float mrow[2][2] = {{-1e30f, -1e30f}, {-1e30f, -1e30f}};
    float lrow[2][2] = {{0.f, 0.f}, {0.f, 0.f}};

#pragma unroll
    for (int u = 0; u < 8; ++u) {
        const int e = tid + 256 * u;
        const int row = e >> 4, j = e & 15;
        const __nv_bfloat16* src = (j < 8 ? g_qh : g_ql) + qbase
                                 + (size_t)row * CHD + (j & 7) * 8;
        cp16(qs_b + row * 272 + j * 16, src);
    }
    issueKV(0, 0);
    issueKV(1, 1);

    for (int kt = 0; kt < 16; ++kt) {
        if (kt < 15) cp_wait1(); else cp_wait0();
        __syncthreads();
        if (kt + 2 < 16) issueKV(kt + 2, (kt + 2) % 3);
        const uint32_t sK = (kt % 3) * KSB2;
        const uint32_t sV = (kt % 3) * VSBH;

        // ---- S = Q K^T : bf16 3-term ----
        float sc[2][4][4];
#pragma unroll
        for (int mi = 0; mi < 2; ++mi)
#pragma unroll
            for (int f = 0; f < 4; ++f)
#pragma unroll
                for (int q = 0; q < 4; ++q) sc[mi][f][q] = 0.f;
#pragma unroll
        for (int ks = 0; ks < 4; ++ks) {
            uint32_t qhf[2][4], qlf[2][4];
#pragma unroll
            for (int mi = 0; mi < 2; ++mi) {
                const uint32_t aa = a_base + mi * 16 * 272 + ks * 32;
                ldsm_x4(qhf[mi][0], qhf[mi][1], qhf[mi][2], qhf[mi][3], aa);
                ldsm_x4(qlf[mi][0], qlf[mi][1], qlf[mi][2], qlf[mi][3], aa + 128);
            }
#pragma unroll
            for (int nj = 0; nj < 2; ++nj) {
                const uint32_t bb = kfrag + sK + nj * 16 * 272 + ks * 32;
                uint32_t kh0, kh1, kh2, kh3, kl0, kl1, kl2, kl3;
                ldsm_x4(kh0, kh1, kh2, kh3, bb);
                ldsm_x4(kl0, kl1, kl2, kl3, bb + 128);
#pragma unroll
                for (int mi = 0; mi < 2; ++mi) {
                    float* s0 = sc[mi][nj * 2];
                    float* s1 = sc[mi][nj * 2 + 1];
                    mma16816(s0, qhf[mi], kh0, kh1);
                    mma16816(s0, qlf[mi], kh0, kh1);
                    mma16816(s0, qhf[mi], kl0, kl1);
                    mma16816(s1, qhf[mi], kh2, kh3);
                    mma16816(s1, qlf[mi], kh2, kh3);
                    mma16816(s1, qhf[mi], kl2, kl3);
                }
            }
        }

        // ---- online-max softmax, log2 domain, rescale skip ----
#pragma unroll
        for (int mi = 0; mi < 2; ++mi) {
            float mt0 = -1e30f, mt1 = -1e30f;
#pragma unroll
            for (int f = 0; f < 4; ++f) {
                mt0 = fmaxf(mt0, fmaxf(sc[mi][f][0], sc[mi][f][1]));
                mt1 = fmaxf(mt1, fmaxf(sc[mi][f][2], sc[mi][f][3]));
            }
            mt0 = fmaxf(mt0, __shfl_xor_sync(0xffffffffu, mt0, 1));
            mt0 = fmaxf(mt0, __shfl_xor_sync(0xffffffffu, mt0, 2));
            mt1 = fmaxf(mt1, __shfl_xor_sync(0xffffffffu, mt1, 1));
            mt1 = fmaxf(mt1, __shfl_xor_sync(0xffffffffu, mt1, 2));

            const bool upd = __any_sync(0xffffffffu,
                (mt0 > mrow[mi][0]) || (mt1 > mrow[mi][1]));
            float mn0 = mrow[mi][0], mn1 = mrow[mi][1];
            if (upd) {
                mn0 = fmaxf(mrow[mi][0], mt0);
                mn1 = fmaxf(mrow[mi][1], mt1);
                const float e0 = ex2f(mrow[mi][0] - mn0);
                const float e1 = ex2f(mrow[mi][1] - mn1);
                mrow[mi][0] = mn0; mrow[mi][1] = mn1;
                lrow[mi][0] *= e0; lrow[mi][1] *= e1;
#pragma unroll
                for (int f = 0; f < 8; ++f) {
                    oc[mi][f][0] *= e0; oc[mi][f][1] *= e0;
                    oc[mi][f][2] *= e1; oc[mi][f][3] *= e1;
                }
            }
            float rs0 = 0.f, rs1 = 0.f;
#pragma unroll
            for (int f = 0; f < 4; ++f) {
                sc[mi][f][0] = ex2f(sc[mi][f][0] - mn0); rs0 += sc[mi][f][0];
                sc[mi][f][1] = ex2f(sc[mi][f][1] - mn0); rs0 += sc[mi][f][1];
                sc[mi][f][2] = ex2f(sc[mi][f][2] - mn1); rs1 += sc[mi][f][2];
                sc[mi][f][3] = ex2f(sc[mi][f][3] - mn1); rs1 += sc[mi][f][3];
            }
            lrow[mi][0] += rs0; lrow[mi][1] += rs1;
        }

        // ---- O += P V : fp16 single ----
#pragma unroll
        for (int ks = 0; ks < 2; ++ks) {
            uint32_t ph[2][4];
#pragma unroll
            for (int mi = 0; mi < 2; ++mi) {
                ph[mi][0] = packh(sc[mi][2 * ks][0],     sc[mi][2 * ks][1]);
                ph[mi][1] = packh(sc[mi][2 * ks][2],     sc[mi][2 * ks][3]);
                ph[mi][2] = packh(sc[mi][2 * ks + 1][0], sc[mi][2 * ks + 1][1]);
                ph[mi][3] = packh(sc[mi][2 * ks + 1][2], sc[mi][2 * ks + 1][3]);
            }
#pragma unroll
            for (int nj = 0; nj < 4; ++nj) {
                const uint32_t bb = vfrag + sV + nj * 16 * 144 + ks * 32;
                uint32_t vh0, vh1, vh2, vh3;
                ldsm_x4(vh0, vh1, vh2, vh3, bb);
#pragma unroll
                for (int mi = 0; mi < 2; ++mi) {
                    mma16816h(oc[mi][nj * 2],     ph[mi], vh0, vh1);
                    mma16816h(oc[mi][nj * 2 + 1], ph[mi], vh2, vh3);
                }
            }
        }
    }

    // ---- quad-reduce partial l ----
#pragma unroll
    for (int mi = 0; mi < 2; ++mi)
#pragma unroll
        for (int r = 0; r < 2; ++r) {
            lrow[mi][r] += __shfl_xor_sync(0xffffffffu, lrow[mi][r], 1);
            lrow[mi][r] += __shfl_xor_sync(0xffffffffu, lrow[mi][r], 2);
        }

    // ---- cross-key-group merge with max rescale (log2 domain) ----
    float* red = (float*)dsm + (wm * 32 + lane) * 72;
    __syncthreads();
    if (wk == 1) {
#pragma unroll
        for (int mi = 0; mi < 2; ++mi)
#pragma unroll
            for (int f = 0; f < 8; ++f)
#pragma unroll
                for (int q = 0; q < 4; ++q)
                    red[mi * 32 + f * 4 + q] = oc[mi][f][q];
        red[64] = lrow[0][0]; red[65] = lrow[0][1];
        red[66] = lrow[1][0]; red[67] = lrow[1][1];
        red[68] = mrow[0][0]; red[69] = mrow[0][1];
        red[70] = mrow[1][0]; red[71] = mrow[1][1];
    }
    __syncthreads();
    if (wk == 1) return;

#pragma unroll
    for (int mi = 0; mi < 2; ++mi)
#pragma unroll
        for (int rh = 0; rh < 2; ++rh) {
            const float mB = red[68 + mi * 2 + rh];
            const float lB = red[64 + mi * 2 + rh];
            const float mM = fmaxf(mrow[mi][rh], mB);
            const float sA = ex2f(mrow[mi][rh] - mM);
            const float sB = ex2f(mB - mM);
            lrow[mi][rh] = lrow[mi][rh] * sA + lB * sB;
#pragma unroll
            for (int f = 0; f < 8; ++f)
#pragma unroll
                for (int q = rh * 2; q < rh * 2 + 2; ++q)
                    oc[mi][f][q] = oc[mi][f][q] * sA
                                 + red[mi * 32 + f * 4 + q] * sB;
        }

    // ---- epilogue: normalize + post-scale -> fp16 single g_ash ----
    const float post = 0.03608439182435161f;   // 1/sqrt(768)
    const int b = bh / CH;
    const int h = bh % CH;
#pragma unroll
    for (int mi = 0; mi < 2; ++mi) {
        const float f0 = post / lrow[mi][0];
        const float f1 = post / lrow[mi][1];
        const size_t R0 = (size_t)(b * CN + q0 + wm * 32 + mi * 16 + r0);
#pragma unroll
        for (int j = 0; j < 8; ++j) {
            const int c = h * 64 + 8 * j + cc;
            *(uint32_t*)(g_ash + R0 * CD + c) =
                packh(oc[mi][j][0] * f0, oc[mi][j][1] * f0);
            *(uint32_t*)(g_ash + (R0 + 8) * CD + c) =
                packh(oc[mi][j][2] * f1, oc[mi][j][3] * f1);
        }
    }
}

// ---------------------------------------------------------------------------
extern "C" void kernel_launch(void* const* d_in, const int* in_sizes, int n_in,
                              void* d_out, int out_size)
{
    (void)in_sizes; (void)n_in; (void)out_size;
    const float* x  = (const float*)d_in[0];
    const float* Wq = (const float*)d_in[1];
    const float* bq = (const float*)d_in[2];
    const float* Wk = (const float*)d_in[3];
    const float* bk = (const float*)d_in[4];
    const float* Wv = (const float*)d_in[5];
    const float* bv = (const float*)d_in[6];
    const float* Wo = (const float*)d_in[7];
    const float* bo = (const float*)d_in[8];
    float* out = (float*)d_out;

    cudaFuncSetAttribute(gemm_qkv,
                         cudaFuncAttributeMaxDynamicSharedMemorySize, QKV_SMEM);
    cudaFuncSetAttribute(attn_mma_kernel,
                         cudaFuncAttributeMaxDynamicSharedMemorySize, ATT_SMEM);

    prep_kernel<<<PREP_BLOCKS, 256>>>(x, Wq, Wk, Wv, Wo);
    gemm_qkv<<<dim3(6, 64, 3), 256, QKV_SMEM>>>(bq, bk, bv);
    attn_mma_kernel<<<dim3(CN / 128, BH), 256, ATT_SMEM>>>();
    gemm_o<<<dim3(6, 128), 256>>>(bo, out);
}